// round 13
// baseline (speedup 1.0000x reference)
#include <cuda_runtime.h>
#include <cuda_fp16.h>
#include <math_constants.h>

// Fused GAT forward, phase-split edition (R11 + alignment fix).
// N=50000, deg=16 (CSR), H=4, D=32.
//
// K1 (merged, two block roles):
//   - score blocks (first SB): warp per node pair. 4 lanes per edge load one
//     attn_col head-word each (all attn LDGs coalesce @1.0 cyc/line).
//     Distributed softmax via xor-shuffle strides 4/8/16 (head fixed per
//     lane). Alphas paired {a_p, a_{p+2}} via shfl_xor(.,2) -> g_alpha.
//   - convert blocks (next CB): in_feat fp32 -> g_feat16 fp16 (uint4 stores).
// K2 (aggregation only): warp per node. Coalesced reload of alpha + cols
//   into smem (pad 18 float2 = 144B so float4 LDS stays 16B-aligned!),
//   then one-line-per-LDG.32 fp16 gather: lane owns words {col*64+l} and
//   {col*64+32+l}. fp32 accumulate, coalesced float2 stores.

#define NEG_SLOPE 0.2f
#define MAX_N 50000

__device__ __align__(16) unsigned int g_feat16[(size_t)MAX_N * 64]; // fp16 feats
__device__ __align__(16) float2 g_alpha[(size_t)MAX_N * 32];        // [node][p][e]

// =================== K1: scores + convert (merged) ===================
__global__ void __launch_bounds__(256, 5)
gat_score_convert_kernel(const float*  __restrict__ attn_row,   // [N,4]
                         const float*  __restrict__ attn_col,   // [N,4]
                         const int*    __restrict__ row_indptr, // [N+1]
                         const int*    __restrict__ col_idx,    // [E]
                         const float4* __restrict__ feat_src,   // in_feat as float4
                         int n, int score_blocks, int n8)
{
    const unsigned FULL = 0xffffffffu;

    if ((int)blockIdx.x >= score_blocks) {
        // ---------------- convert role ----------------
        int i = (blockIdx.x - score_blocks) * 256 + threadIdx.x;
        if (i < n8) {
            const float4 a = feat_src[2 * i];
            const float4 b = feat_src[2 * i + 1];
            const __half2 h0 = __floats2half2_rn(a.x, a.y);
            const __half2 h1 = __floats2half2_rn(a.z, a.w);
            const __half2 h2 = __floats2half2_rn(b.x, b.y);
            const __half2 h3 = __floats2half2_rn(b.z, b.w);
            uint4 u;
            u.x = *reinterpret_cast<const unsigned int*>(&h0);
            u.y = *reinterpret_cast<const unsigned int*>(&h1);
            u.z = *reinterpret_cast<const unsigned int*>(&h2);
            u.w = *reinterpret_cast<const unsigned int*>(&h3);
            ((uint4*)g_feat16)[i] = u;
        }
        return;
    }

    // ---------------- score role: warp per node pair ----------------
    const int lane  = threadIdx.x & 31;
    const int w     = threadIdx.x >> 5;
    const int pair  = blockIdx.x * 8 + w;
    const int node0 = pair * 2;
    if (node0 >= n) return;

    const bool v1 = (node0 + 1) < n;

    // indptr for node0, node0+1, node0+2 (clamped)
    int ipv = 0;
    if (lane < 3) {
        int idx = node0 + lane; if (idx > n) idx = n;
        ipv = __ldg(&row_indptr[idx]);
    }
    const int ip0  = __shfl_sync(FULL, ipv, 0);
    const int ip1  = __shfl_sync(FULL, ipv, 1);
    const int ip2  = __shfl_sync(FULL, ipv, 2);
    const int deg0 = ip1 - ip0;
    const int deg1 = v1 ? (ip2 - ip1) : 0;

    // lane l holds col for edge E = l  (el = l&15, half = l>>4)
    const int  el   = lane & 15;
    const int  half = lane >> 4;
    const bool ve_l = half ? (v1 && el < deg1) : (el < deg0);
    int col_l = 0;
    if (ve_l) col_l = __ldg(&col_idx[(half ? ip1 : ip0) + el]);

    // attn_row words for both nodes (8 words); lane<8 loads
    float arw = 0.f;
    if (lane < 8) arw = __ldg(&attn_row[node0 * 4 + lane]);

    // scores: reg i covers edge E = i*8 + lane>>2, head h = lane&3
    const int h    = lane & 3;
    const int esub = lane >> 2;             // 0..7
    float s[4];
    #pragma unroll
    for (int i = 0; i < 4; ++i) {
        const int  E  = i * 8 + esub;
        const int  hf = E >> 4;
        const bool vE = hf ? (v1 && (E & 15) < deg1) : (E < deg0);
        const int  cE = __shfl_sync(FULL, col_l, E);
        float ac = 0.f;
        if (vE) ac = __ldg(&attn_col[cE * 4 + h]);
        const float ari = __shfl_sync(FULL, arw, (hf << 2) + h);
        float t = ari + ac;
        t = (t > 0.f) ? t : NEG_SLOPE * t;
        s[i] = vE ? t : -CUDART_INF_F;
    }

    // softmax node A (regs 0,1) and node B (regs 2,3); strides 4,8,16
    float mA = fmaxf(s[0], s[1]);
    float mB = fmaxf(s[2], s[3]);
    #pragma unroll
    for (int k = 4; k <= 16; k <<= 1) {
        mA = fmaxf(mA, __shfl_xor_sync(FULL, mA, k));
        mB = fmaxf(mB, __shfl_xor_sync(FULL, mB, k));
    }

    float a[4];
    a[0] = __expf(s[0] - mA);
    a[1] = __expf(s[1] - mA);
    a[2] = __expf(s[2] - mB);
    a[3] = __expf(s[3] - mB);

    float dA = a[0] + a[1];
    float dB = a[2] + a[3];
    #pragma unroll
    for (int k = 4; k <= 16; k <<= 1) {
        dA += __shfl_xor_sync(FULL, dA, k);
        dB += __shfl_xor_sync(FULL, dB, k);
    }
    const float iA = __fdividef(1.f, dA);
    const float iB = __fdividef(1.f, dB);
    a[0] *= iA; a[1] *= iA;
    a[2] *= iB; a[3] *= iB;

    // pair heads (h, h+2) via shfl_xor(2); lanes with h<2 write {a_h, a_{h+2}}
    #pragma unroll
    for (int i = 0; i < 4; ++i) {
        const float pa = __shfl_xor_sync(FULL, a[i], 2);
        if (!(lane & 2) && (i < 2 || v1)) {
            const int nE  = node0 + (i >> 1);
            const int elE = (i & 1) * 8 + esub;
            const int pp  = lane & 1;
            g_alpha[(size_t)nE * 32 + pp * 16 + elE] = make_float2(a[i], pa);
        }
    }
}

// =================== K2: aggregation only ===================
__global__ void __launch_bounds__(256, 6)
gat_aggregate_kernel(const int* __restrict__ row_indptr, // [N+1]
                     const int* __restrict__ col_idx,    // [E]
                     float*     __restrict__ out,        // [N,4,32]
                     int n)
{
    __shared__ __align__(16) int    s_col[8][16];
    // pad 18 (144B): keeps &s_ap[w][p][0] 16B-aligned for float4 LDS.
    __shared__ __align__(16) float2 s_ap[8][2][18];

    const int lane = threadIdx.x & 31;
    const int w    = threadIdx.x >> 5;
    const int node = blockIdx.x * 8 + w;
    if (node >= n) return;

    const int start = __ldg(&row_indptr[node]);
    const int deg   = __ldg(&row_indptr[node + 1]) - start;

    // cols -> smem (lanes 0..15), invalid edges -> col 0 (alpha is 0)
    if (lane < 16)
        s_col[w][lane] = (lane < deg) ? __ldg(&col_idx[start + lane]) : 0;

    // alphas -> smem: 32 float2 per node, one per lane, coalesced (2 lines)
    {
        const float2 av = __ldg(&g_alpha[(size_t)node * 32 + lane]);
        s_ap[w][lane >> 4][lane & 15] = av;
    }
    __syncwarp(0xffffffffu);

    // gather: lane owns fp16 words {l} and {32+l} of each 64-word row
    const int p = lane >> 4;                       // low head p, high head p+2
    const int4*   __restrict__ cp = (const int4*)s_col[w];
    const float4* __restrict__ ap = (const float4*)&s_ap[w][p][0];
    const unsigned int* __restrict__ fb = g_feat16;

    float2 accL = make_float2(0.f, 0.f);
    float2 accH = make_float2(0.f, 0.f);

    #pragma unroll
    for (int j4 = 0; j4 < 4; ++j4) {
        const int4   c  = cp[j4];          // 4 neighbor ids (broadcast)
        const float4 A0 = ap[j4 * 2];      // edges 0,1: {aL,aH,aL,aH}
        const float4 A1 = ap[j4 * 2 + 1];  // edges 2,3

        unsigned b, u0, u1;
        float2 f0, f1;

        b  = (unsigned)c.x * 64u;
        u0 = __ldg(fb + b + lane);
        u1 = __ldg(fb + b + 32 + lane);
        f0 = __half22float2(*reinterpret_cast<const __half2*>(&u0));
        f1 = __half22float2(*reinterpret_cast<const __half2*>(&u1));
        accL.x = fmaf(A0.x, f0.x, accL.x); accL.y = fmaf(A0.x, f0.y, accL.y);
        accH.x = fmaf(A0.y, f1.x, accH.x); accH.y = fmaf(A0.y, f1.y, accH.y);

        b  = (unsigned)c.y * 64u;
        u0 = __ldg(fb + b + lane);
        u1 = __ldg(fb + b + 32 + lane);
        f0 = __half22float2(*reinterpret_cast<const __half2*>(&u0));
        f1 = __half22float2(*reinterpret_cast<const __half2*>(&u1));
        accL.x = fmaf(A0.z, f0.x, accL.x); accL.y = fmaf(A0.z, f0.y, accL.y);
        accH.x = fmaf(A0.w, f1.x, accH.x); accH.y = fmaf(A0.w, f1.y, accH.y);

        b  = (unsigned)c.z * 64u;
        u0 = __ldg(fb + b + lane);
        u1 = __ldg(fb + b + 32 + lane);
        f0 = __half22float2(*reinterpret_cast<const __half2*>(&u0));
        f1 = __half22float2(*reinterpret_cast<const __half2*>(&u1));
        accL.x = fmaf(A1.x, f0.x, accL.x); accL.y = fmaf(A1.x, f0.y, accL.y);
        accH.x = fmaf(A1.y, f1.x, accH.x); accH.y = fmaf(A1.y, f1.y, accH.y);

        b  = (unsigned)c.w * 64u;
        u0 = __ldg(fb + b + lane);
        u1 = __ldg(fb + b + 32 + lane);
        f0 = __half22float2(*reinterpret_cast<const __half2*>(&u0));
        f1 = __half22float2(*reinterpret_cast<const __half2*>(&u1));
        accL.x = fmaf(A1.z, f0.x, accL.x); accL.y = fmaf(A1.z, f0.y, accL.y);
        accH.x = fmaf(A1.w, f1.x, accH.x); accH.y = fmaf(A1.w, f1.y, accH.y);
    }

    // out[node]: float2 at dims {2l,2l+1} and {64+2l,65+2l} (coalesced)
    float2* op = (float2*)out + (size_t)node * 64;
    op[lane]      = accL;
    op[32 + lane] = accH;
}

extern "C" void kernel_launch(void* const* d_in, const int* in_sizes, int n_in,
                              void* d_out, int out_size)
{
    const float* attn_row   = (const float*)d_in[0];
    const float* attn_col   = (const float*)d_in[1];
    const float* in_feat    = (const float*)d_in[2];
    const int*   row_indptr = (const int*)  d_in[3];
    const int*   col_idx    = (const int*)  d_in[4];
    float*       out        = (float*)      d_out;

    const int n  = in_sizes[3] - 1;   // N from indptr length
    const int n8 = in_sizes[2] / 8;   // uint4 count of fp16 copy

    const int pairs = (n + 1) / 2;
    const int SB = (pairs + 7) / 8;           // score blocks (8 warps each)
    const int CB = (n8 + 255) / 256;          // convert blocks

    gat_score_convert_kernel<<<SB + CB, 256>>>(attn_row, attn_col,
                                               row_indptr, col_idx,
                                               (const float4*)in_feat,
                                               n, SB, n8);

    gat_aggregate_kernel<<<(n + 7) / 8, 256>>>(row_indptr, col_idx, out, n);
}

// round 14
// speedup vs baseline: 1.0046x; 1.0046x over previous
#include <cuda_runtime.h>
#include <cuda_fp16.h>
#include <math_constants.h>

// Fused GAT forward, prefetch edition. N=50000, deg=16 (CSR), H=4, D=32.
//
// K1 (convert): in_feat fp32 [N,128] -> g_feat16 fp16 words (uint4 stores).
// K2 (gat), warp per node, GATHER-FIRST:
//   1. load col_idx (lanes 0..15)
//   2. broadcast cols and IMMEDIATELY issue all 32 feature LDG.32s into
//      registers (each spans exactly one 128B line). They fly during...
//   3. ...attn_col gather + leaky-relu + xor-shuffle softmax + smem alpha
//      park (the ~400cyc score phase) -> per-warp gather latency hidden.
//   4. consume: LDS.128 alpha pairs, cvt fp16->fp32, FFMA, coalesced stores.
//   __launch_bounds__(256,4): 64-reg cap holds 32 prefetch regs without
//   spilling; 50% occ is enough once latency is register-hidden (R8 evidence).

#define NEG_SLOPE 0.2f
#define WPB 8
#define MAX_N 50000

__device__ __align__(16) unsigned int g_feat16[(size_t)MAX_N * 64];

// ---------------- fp32 -> fp16 conversion pre-pass ----------------
__global__ void __launch_bounds__(256)
gat_convert_kernel(const float4* __restrict__ src, int n8)
{
    int i = blockIdx.x * blockDim.x + threadIdx.x;
    if (i >= n8) return;
    const float4 a = src[2 * i];
    const float4 b = src[2 * i + 1];
    const __half2 h0 = __floats2half2_rn(a.x, a.y);
    const __half2 h1 = __floats2half2_rn(a.z, a.w);
    const __half2 h2 = __floats2half2_rn(b.x, b.y);
    const __half2 h3 = __floats2half2_rn(b.z, b.w);
    uint4 u;
    u.x = *reinterpret_cast<const unsigned int*>(&h0);
    u.y = *reinterpret_cast<const unsigned int*>(&h1);
    u.z = *reinterpret_cast<const unsigned int*>(&h2);
    u.w = *reinterpret_cast<const unsigned int*>(&h3);
    ((uint4*)g_feat16)[i] = u;
}

// ---------------- main fused GAT kernel ----------------
__global__ void __launch_bounds__(WPB * 32, 4)
fused_gat_prefetch_kernel(const float* __restrict__ attn_row,   // [N,4]
                          const float* __restrict__ attn_col,   // [N,4]
                          const int*   __restrict__ row_indptr, // [N+1]
                          const int*   __restrict__ col_idx,    // [E]
                          float*       __restrict__ out,        // [N,4,32]
                          int n)
{
    const unsigned FULL = 0xffffffffu;
    // pad 18 (144B): &s_ap[w][p][0] stays 16B-aligned for float4 LDS
    __shared__ __align__(16) float2 s_ap[WPB][2][18];

    const int lane = threadIdx.x & 31;
    const int w    = threadIdx.x >> 5;
    const int node = blockIdx.x * WPB + w;
    if (node >= n) return;

    // attn_row: independent of cols, issue first
    const float4 ar = __ldg((const float4*)attn_row + node);

    const int start = __ldg(&row_indptr[node]);
    const int deg   = __ldg(&row_indptr[node + 1]) - start;   // == 16 here

    const bool edge_lane = (lane < 16) && (lane < deg);
    int col = 0;
    if (edge_lane) col = __ldg(&col_idx[start + lane]);

    // attn_col gather (critical path for softmax) — issue before prefetch
    float4 ac = make_float4(0.f, 0.f, 0.f, 0.f);
    if (edge_lane) ac = __ldg((const float4*)attn_col + col);

    // ---- PREFETCH: all 32 feature words, in flight during softmax ----
    const unsigned int* __restrict__ fb = g_feat16;
    unsigned uL[16], uH[16];
    #pragma unroll
    for (int j = 0; j < 16; ++j) {
        const unsigned b = (unsigned)__shfl_sync(FULL, col, j) * 64u;
        uL[j] = __ldg(fb + b + lane);        // line 0 of neighbor row
        uH[j] = __ldg(fb + b + 32 + lane);   // line 1 of neighbor row
    }

    // ---- scores, all 4 heads (lanes 0..15) ----
    float s0 = -CUDART_INF_F, s1 = -CUDART_INF_F,
          s2 = -CUDART_INF_F, s3 = -CUDART_INF_F;
    if (edge_lane) {
        float t0 = ar.x + ac.x, t1 = ar.y + ac.y;
        float t2 = ar.z + ac.z, t3 = ar.w + ac.w;
        s0 = (t0 > 0.0f) ? t0 : NEG_SLOPE * t0;
        s1 = (t1 > 0.0f) ? t1 : NEG_SLOPE * t1;
        s2 = (t2 > 0.0f) ? t2 : NEG_SLOPE * t2;
        s3 = (t3 > 0.0f) ? t3 : NEG_SLOPE * t3;
    }

    // ---- shuffle softmax over 16-edge group (xor 8,4,2,1; halves isolated) ----
    float m0 = s0, m1 = s1, m2 = s2, m3 = s3;
    #pragma unroll
    for (int k = 8; k > 0; k >>= 1) {
        m0 = fmaxf(m0, __shfl_xor_sync(FULL, m0, k));
        m1 = fmaxf(m1, __shfl_xor_sync(FULL, m1, k));
        m2 = fmaxf(m2, __shfl_xor_sync(FULL, m2, k));
        m3 = fmaxf(m3, __shfl_xor_sync(FULL, m3, k));
    }

    float e0 = 0.f, e1 = 0.f, e2 = 0.f, e3 = 0.f;
    if (edge_lane) {
        e0 = __expf(s0 - m0);
        e1 = __expf(s1 - m1);
        e2 = __expf(s2 - m2);
        e3 = __expf(s3 - m3);
    }

    float d0 = e0, d1 = e1, d2 = e2, d3 = e3;
    #pragma unroll
    for (int k = 8; k > 0; k >>= 1) {
        d0 += __shfl_xor_sync(FULL, d0, k);
        d1 += __shfl_xor_sync(FULL, d1, k);
        d2 += __shfl_xor_sync(FULL, d2, k);
        d3 += __shfl_xor_sync(FULL, d3, k);
    }

    if (lane < 16) {
        s_ap[w][0][lane] = make_float2(__fdividef(e0, d0), __fdividef(e2, d2));
        s_ap[w][1][lane] = make_float2(__fdividef(e1, d1), __fdividef(e3, d3));
    }
    __syncwarp(FULL);

    // ---- consume prefetched features ----
    const int p = lane >> 4;   // low-word head p, high-word head p+2
    const float4* __restrict__ ap = (const float4*)&s_ap[w][p][0];

    float2 accL = make_float2(0.f, 0.f);
    float2 accH = make_float2(0.f, 0.f);

    #pragma unroll
    for (int j4 = 0; j4 < 4; ++j4) {
        const float4 A0 = ap[j4 * 2];      // edges 4j4, 4j4+1: {aL,aH,aL,aH}
        const float4 A1 = ap[j4 * 2 + 1];  // edges 4j4+2, 4j4+3
        const int e = j4 * 4;

        float2 f;
        f = __half22float2(*reinterpret_cast<const __half2*>(&uL[e]));
        accL.x = fmaf(A0.x, f.x, accL.x); accL.y = fmaf(A0.x, f.y, accL.y);
        f = __half22float2(*reinterpret_cast<const __half2*>(&uH[e]));
        accH.x = fmaf(A0.y, f.x, accH.x); accH.y = fmaf(A0.y, f.y, accH.y);

        f = __half22float2(*reinterpret_cast<const __half2*>(&uL[e + 1]));
        accL.x = fmaf(A0.z, f.x, accL.x); accL.y = fmaf(A0.z, f.y, accL.y);
        f = __half22float2(*reinterpret_cast<const __half2*>(&uH[e + 1]));
        accH.x = fmaf(A0.w, f.x, accH.x); accH.y = fmaf(A0.w, f.y, accH.y);

        f = __half22float2(*reinterpret_cast<const __half2*>(&uL[e + 2]));
        accL.x = fmaf(A1.x, f.x, accL.x); accL.y = fmaf(A1.x, f.y, accL.y);
        f = __half22float2(*reinterpret_cast<const __half2*>(&uH[e + 2]));
        accH.x = fmaf(A1.y, f.x, accH.x); accH.y = fmaf(A1.y, f.y, accH.y);

        f = __half22float2(*reinterpret_cast<const __half2*>(&uL[e + 3]));
        accL.x = fmaf(A1.z, f.x, accL.x); accL.y = fmaf(A1.z, f.y, accL.y);
        f = __half22float2(*reinterpret_cast<const __half2*>(&uH[e + 3]));
        accH.x = fmaf(A1.w, f.x, accH.x); accH.y = fmaf(A1.w, f.y, accH.y);
    }

    // out[node]: float2 at dims {2l,2l+1} and {64+2l,65+2l} (coalesced)
    float2* op = (float2*)out + (size_t)node * 64;
    op[lane]      = accL;
    op[32 + lane] = accH;
}

extern "C" void kernel_launch(void* const* d_in, const int* in_sizes, int n_in,
                              void* d_out, int out_size)
{
    const float* attn_row   = (const float*)d_in[0];
    const float* attn_col   = (const float*)d_in[1];
    const float* in_feat    = (const float*)d_in[2];
    const int*   row_indptr = (const int*)  d_in[3];
    const int*   col_idx    = (const int*)  d_in[4];
    float*       out        = (float*)      d_out;

    const int n  = in_sizes[3] - 1;   // N from indptr length
    const int n8 = in_sizes[2] / 8;   // uint4 count of fp16 copy

    gat_convert_kernel<<<(n8 + 255) / 256, 256>>>((const float4*)in_feat, n8);

    fused_gat_prefetch_kernel<<<(n + WPB - 1) / WPB, WPB * 32>>>(
        attn_row, attn_col, row_indptr, col_idx, out, n);
}

// round 15
// speedup vs baseline: 1.2015x; 1.1961x over previous
#include <cuda_runtime.h>
#include <cuda_fp16.h>
#include <math_constants.h>

// Fused GAT forward. N=50000, deg=16 (CSR), H=4, D=32.
//
// K1 (convert, PDL primary): in_feat fp32 -> g_feat16 fp16 (uint4 stores).
//   Executes griddepcontrol.launch_dependents at ENTRY so the dependent
//   kernel starts while conversion is still running.
// K2 (gat, PDL secondary, R9's best-main verbatim): warp per NODE PAIR.
//   Score phase (indptr, col_idx, attn gathers, xor-shuffle softmax, smem
//   alpha park) touches nothing the convert writes -> runs concurrently
//   with K1. griddepcontrol.wait right before the g_feat16 gather.
//   Aggregation: lane owns fp16 words {col*64+l} and {col*64+32+l}; every
//   gather LDG.32 covers exactly one 128B line. fp32 accumulate.

#define NEG_SLOPE 0.2f
#define WPB 8
#define MAX_N 50000

__device__ __align__(16) unsigned int g_feat16[(size_t)MAX_N * 64];

// ---------------- K1: fp32 -> fp16 convert (PDL primary) ----------------
__global__ void __launch_bounds__(256)
gat_convert_kernel(const float4* __restrict__ src, int n8)
{
    // Let the dependent grid start launching immediately.
    asm volatile("griddepcontrol.launch_dependents;" ::: "memory");

    int i = blockIdx.x * blockDim.x + threadIdx.x;
    if (i >= n8) return;
    const float4 a = src[2 * i];
    const float4 b = src[2 * i + 1];
    const __half2 h0 = __floats2half2_rn(a.x, a.y);
    const __half2 h1 = __floats2half2_rn(a.z, a.w);
    const __half2 h2 = __floats2half2_rn(b.x, b.y);
    const __half2 h3 = __floats2half2_rn(b.z, b.w);
    uint4 u;
    u.x = *reinterpret_cast<const unsigned int*>(&h0);
    u.y = *reinterpret_cast<const unsigned int*>(&h1);
    u.z = *reinterpret_cast<const unsigned int*>(&h2);
    u.w = *reinterpret_cast<const unsigned int*>(&h3);
    ((uint4*)g_feat16)[i] = u;
}

// ---------------- K2: fused GAT pair kernel (PDL secondary) ----------------
__global__ void __launch_bounds__(WPB * 32, 4)
fused_gat_pair_kernel(const float* __restrict__ attn_row,   // [N,4]
                      const float* __restrict__ attn_col,   // [N,4]
                      const int*   __restrict__ row_indptr, // [N+1]
                      const int*   __restrict__ col_idx,    // [E]
                      float*       __restrict__ out,        // [N,4,32]
                      int n)
{
    const unsigned FULL = 0xffffffffu;
    __shared__ __align__(16) int    s_col[WPB][32];
    // [warp][p][node-half][edge(16 padded to 18)] : {alpha_p, alpha_{p+2}}
    __shared__ __align__(16) float2 s_ap[WPB][2][2][18];

    const int lane  = threadIdx.x & 31;
    const int w     = threadIdx.x >> 5;
    const int pair  = blockIdx.x * WPB + w;
    const int node0 = pair * 2;
    if (node0 >= n) return;

    const int  half = lane >> 4;        // which node of the pair my lane scores
    const int  el   = lane & 15;        // edge slot within that node
    int        node = node0 + half;
    const bool nvalid = (node < n);
    if (!nvalid) node = n - 1;          // clamp for safe loads

    const int start = __ldg(&row_indptr[node]);
    const int deg   = __ldg(&row_indptr[node + 1]) - start;

    // ---- per-edge scores, all 4 heads (independent of g_feat16!) ----
    const float4 ar = __ldg((const float4*)attn_row + node);

    int col = 0;
    float s0 = -CUDART_INF_F, s1 = -CUDART_INF_F,
          s2 = -CUDART_INF_F, s3 = -CUDART_INF_F;

    const bool edge_lane = nvalid && (el < deg);
    if (edge_lane) {
        col = __ldg(&col_idx[start + el]);
        const float4 ac = __ldg((const float4*)attn_col + col);
        float t0 = ar.x + ac.x, t1 = ar.y + ac.y;
        float t2 = ar.z + ac.z, t3 = ar.w + ac.w;
        s0 = (t0 > 0.0f) ? t0 : NEG_SLOPE * t0;
        s1 = (t1 > 0.0f) ? t1 : NEG_SLOPE * t1;
        s2 = (t2 > 0.0f) ? t2 : NEG_SLOPE * t2;
        s3 = (t3 > 0.0f) ? t3 : NEG_SLOPE * t3;
    }

    // ---- shuffle softmax per 16-lane half (xor 8,4,2,1 stays in half) ----
    float m0 = s0, m1 = s1, m2 = s2, m3 = s3;
    #pragma unroll
    for (int k = 8; k > 0; k >>= 1) {
        m0 = fmaxf(m0, __shfl_xor_sync(FULL, m0, k));
        m1 = fmaxf(m1, __shfl_xor_sync(FULL, m1, k));
        m2 = fmaxf(m2, __shfl_xor_sync(FULL, m2, k));
        m3 = fmaxf(m3, __shfl_xor_sync(FULL, m3, k));
    }

    float e0 = 0.f, e1 = 0.f, e2 = 0.f, e3 = 0.f;
    if (edge_lane) {
        e0 = __expf(s0 - m0);
        e1 = __expf(s1 - m1);
        e2 = __expf(s2 - m2);
        e3 = __expf(s3 - m3);
    }

    float d0 = e0, d1 = e1, d2 = e2, d3 = e3;
    #pragma unroll
    for (int k = 8; k > 0; k >>= 1) {
        d0 += __shfl_xor_sync(FULL, d0, k);
        d1 += __shfl_xor_sync(FULL, d1, k);
        d2 += __shfl_xor_sync(FULL, d2, k);
        d3 += __shfl_xor_sync(FULL, d3, k);
    }

    const float a0 = edge_lane ? __fdividef(e0, d0) : 0.f;
    const float a1 = edge_lane ? __fdividef(e1, d1) : 0.f;
    const float a2 = edge_lane ? __fdividef(e2, d2) : 0.f;
    const float a3 = edge_lane ? __fdividef(e3, d3) : 0.f;

    s_col[w][lane]       = col;
    s_ap[w][0][half][el] = make_float2(a0, a2);   // heads (0,2)
    s_ap[w][1][half][el] = make_float2(a1, a3);   // heads (1,3)
    __syncwarp(FULL);

    // ---- wait for convert kernel's g_feat16 before gathering ----
    asm volatile("griddepcontrol.wait;" ::: "memory");

    // ---- aggregation: lane owns fp16 words {l} and {32+l} of each row ----
    const int p = half;   // low-word head p, high-word head p+2
    const unsigned int* __restrict__ fb = g_feat16;

    #pragma unroll
    for (int n2 = 0; n2 < 2; ++n2) {
        const int nodeX = node0 + n2;
        if (nodeX >= n) break;

        const int4*   __restrict__ cp = (const int4*)&s_col[w][n2 * 16];
        const float4* __restrict__ ap = (const float4*)&s_ap[w][p][n2][0];

        float2 accL = make_float2(0.f, 0.f);
        float2 accH = make_float2(0.f, 0.f);

        #pragma unroll
        for (int j4 = 0; j4 < 4; ++j4) {
            const int4   c  = cp[j4];          // 4 neighbor ids (broadcast)
            const float4 A0 = ap[j4 * 2];      // edges 0,1: {aL,aH,aL,aH}
            const float4 A1 = ap[j4 * 2 + 1];  // edges 2,3

            unsigned b, u0, u1;
            float2 f0, f1;

            b  = (unsigned)c.x * 64u;
            u0 = __ldg(fb + b + lane);
            u1 = __ldg(fb + b + 32 + lane);
            f0 = __half22float2(*reinterpret_cast<const __half2*>(&u0));
            f1 = __half22float2(*reinterpret_cast<const __half2*>(&u1));
            accL.x = fmaf(A0.x, f0.x, accL.x); accL.y = fmaf(A0.x, f0.y, accL.y);
            accH.x = fmaf(A0.y, f1.x, accH.x); accH.y = fmaf(A0.y, f1.y, accH.y);

            b  = (unsigned)c.y * 64u;
            u0 = __ldg(fb + b + lane);
            u1 = __ldg(fb + b + 32 + lane);
            f0 = __half22float2(*reinterpret_cast<const __half2*>(&u0));
            f1 = __half22float2(*reinterpret_cast<const __half2*>(&u1));
            accL.x = fmaf(A0.z, f0.x, accL.x); accL.y = fmaf(A0.z, f0.y, accL.y);
            accH.x = fmaf(A0.w, f1.x, accH.x); accH.y = fmaf(A0.w, f1.y, accH.y);

            b  = (unsigned)c.z * 64u;
            u0 = __ldg(fb + b + lane);
            u1 = __ldg(fb + b + 32 + lane);
            f0 = __half22float2(*reinterpret_cast<const __half2*>(&u0));
            f1 = __half22float2(*reinterpret_cast<const __half2*>(&u1));
            accL.x = fmaf(A1.x, f0.x, accL.x); accL.y = fmaf(A1.x, f0.y, accL.y);
            accH.x = fmaf(A1.y, f1.x, accH.x); accH.y = fmaf(A1.y, f1.y, accH.y);

            b  = (unsigned)c.w * 64u;
            u0 = __ldg(fb + b + lane);
            u1 = __ldg(fb + b + 32 + lane);
            f0 = __half22float2(*reinterpret_cast<const __half2*>(&u0));
            f1 = __half22float2(*reinterpret_cast<const __half2*>(&u1));
            accL.x = fmaf(A1.z, f0.x, accL.x); accL.y = fmaf(A1.z, f0.y, accL.y);
            accH.x = fmaf(A1.w, f1.x, accH.x); accH.y = fmaf(A1.w, f1.y, accH.y);
        }

        // out[nodeX]: float2 at dims {2l,2l+1} and {64+2l,65+2l} (coalesced)
        float2* op = (float2*)out + (size_t)nodeX * 64;
        op[lane]      = accL;
        op[32 + lane] = accH;
    }
}

extern "C" void kernel_launch(void* const* d_in, const int* in_sizes, int n_in,
                              void* d_out, int out_size)
{
    const float* attn_row   = (const float*)d_in[0];
    const float* attn_col   = (const float*)d_in[1];
    const float* in_feat    = (const float*)d_in[2];
    const int*   row_indptr = (const int*)  d_in[3];
    const int*   col_idx    = (const int*)  d_in[4];
    float*       out        = (float*)      d_out;

    const int n  = in_sizes[3] - 1;   // N from indptr length
    const int n8 = in_sizes[2] / 8;   // uint4 count of fp16 copy

    // K1: convert (PDL primary, plain launch)
    gat_convert_kernel<<<(n8 + 255) / 256, 256>>>((const float4*)in_feat, n8);

    // K2: fused GAT (PDL secondary — launches while K1 is still running;
    // waits on griddepcontrol.wait just before the feature gather)
    const int pairs  = (n + 1) / 2;
    const int blocks = (pairs + WPB - 1) / WPB;

    cudaLaunchConfig_t cfg = {};
    cfg.gridDim  = dim3(blocks, 1, 1);
    cfg.blockDim = dim3(WPB * 32, 1, 1);
    cfg.dynamicSmemBytes = 0;
    cfg.stream = 0;   // legacy default stream (same as <<<>>>)

    cudaLaunchAttribute attr;
    attr.id = cudaLaunchAttributeProgrammaticStreamSerialization;
    attr.val.programmaticStreamSerializationAllowed = 1;
    cfg.attrs = &attr;
    cfg.numAttrs = 1;

    cudaLaunchKernelEx(&cfg, fused_gat_pair_kernel,
                       attn_row, attn_col, row_indptr, col_idx, out, n);
}